// round 15
// baseline (speedup 1.0000x reference)
#include <cuda_runtime.h>
#include <cuda_fp16.h>
#include <math.h>

typedef unsigned long long ull;

// Problem constants
#define BB   128
#define NN0  64      // positions (j / c / d)
#define DD0  32      // i
#define CC   2048    // channels kz = n1*32 + d1
#define KC   65
#define KVH  8       // kv split factor

// -------- scratch (device globals) --------
__device__ float  g_A [CC * DD0 * NN0];          // A'[o][ci][d]
__device__ __half g_U1[BB * NN0 * CC];           // [b][j][kz] fp16 storage
__device__ __half g_U2[BB * NN0 * CC];
__device__ __half g_U3[BB * NN0 * CC];
__device__ float  g_R1[BB * CC];
__device__ float  g_R2[BB * CC];
__device__ float  g_R3[BB * CC];
__device__ float  g_Spart[BB * NN0 * 64];        // per-warp partials of s[b][j]
__device__ float  g_KVh[KVH * BB * NN0 * NN0];   // split-k kv partials [h][b][c][d]
__device__ float  g_KV [BB * NN0 * NN0];         // reduced kv [b][c][d]
__device__ __half g_Xm[BB * CC * NN0];           // [b][kz][d] fp16 (d contiguous)

// -------- f32x2 helpers --------
__device__ __forceinline__ ull pk2(float lo, float hi) {
    ull r; asm("mov.b64 %0, {%1, %2};" : "=l"(r) : "f"(lo), "f"(hi)); return r;
}
__device__ __forceinline__ void upk2(float& lo, float& hi, ull v) {
    asm("mov.b64 {%0, %1}, %2;" : "=f"(lo), "=f"(hi) : "l"(v));
}
__device__ __forceinline__ void fma2(ull& acc, ull a, ull b) {
    asm("fma.rn.f32x2 %0, %1, %2, %3;" : "=l"(acc) : "l"(a), "l"(b), "l"(acc));
}
__device__ __forceinline__ ull add2(ull a, ull b) {
    ull r; asm("add.rn.f32x2 %0, %1, %2;" : "=l"(r) : "l"(a), "l"(b)); return r;
}

__device__ __forceinline__ float focus_v(float u) {
    return fmaf(fmaxf(u, 0.0f), 0.2f, 2e-7f);   // (relu(u)+1e-6)/5
}
__device__ __forceinline__ float ldh(const __half* p) { return __half2float(*p); }

// -------- K0: A'[o][ci][d] = window-sum of conv_w + identity --------
__global__ void k_prepA(const float* __restrict__ cw) {
    int tid = blockIdx.x * 256 + threadIdx.x;   // 65536
    int o = tid >> 5, ci = tid & 31;
    const float* wr = cw + (o * 32 + ci) * 65;
    float id = (ci == (o & 31)) ? 1.0f : 0.0f;
    float* ar = g_A + (o * 32 + ci) * 64;
    float s = 0.f;
    for (int k = 0; k <= 32; k++) s += wr[k];
    ar[0] = s + id;
    for (int p = 1; p < 64; p++) {
        int addk = p + 32;
        if (addk <= 64) s += wr[addk];
        int rmk = p - 32;
        if (rmk >= 0) s -= wr[rmk];
        ar[p] = s + id;
    }
}

// -------- K1: transform, f32x2 paired over batch; fp16 U stores --------
__global__ __launch_bounds__(128) void k_transform(
    const float* __restrict__ x1, const float* __restrict__ x2, const float* __restrict__ x3,
    const float* __restrict__ W)
{
    __shared__ __align__(16) ull xs[3][64][32];   // b-pairs, 48KB
    int t  = threadIdx.x;
    int j  = blockIdx.y;
    int kz = blockIdx.x * 128 + t;

    for (int e = t; e < 64 * 32; e += 128) {
        int bp = e >> 5, i = e & 31;
        int s0 = (2 * bp) * 2048 + j * 32 + i, s1 = s0 + 2048;
        xs[0][bp][i] = pk2(x1[s0], x1[s1]);
        xs[1][bp][i] = pk2(x2[s0], x2[s1]);
        xs[2][bp][i] = pk2(x3[s0], x3[s1]);
    }

    ull w2[32];
    int wbase = (kz >> 5) * 65536 + j * 1024 + (kz & 31);
#pragma unroll
    for (int i = 0; i < 32; i++) { float w = W[wbase + i * 32]; w2[i] = pk2(w, w); }

    __syncthreads();

    for (int bp = 0; bp < 64; bp++) {
        ull a1 = 0ULL, a2 = 0ULL, a3 = 0ULL;
        const ulonglong2* p0 = (const ulonglong2*)xs[0][bp];
        const ulonglong2* p1 = (const ulonglong2*)xs[1][bp];
        const ulonglong2* p2 = (const ulonglong2*)xs[2][bp];
#pragma unroll
        for (int q = 0; q < 16; q++) {
            ulonglong2 v0 = p0[q], v1 = p1[q], v2 = p2[q];
            fma2(a1, w2[2 * q], v0.x); fma2(a1, w2[2 * q + 1], v0.y);
            fma2(a2, w2[2 * q], v1.x); fma2(a2, w2[2 * q + 1], v1.y);
            fma2(a3, w2[2 * q], v2.x); fma2(a3, w2[2 * q + 1], v2.y);
        }
        float lo, hi;
        int o0 = (2 * bp) * 131072 + j * 2048 + kz, o1 = o0 + 131072;
        upk2(lo, hi, a1); g_U1[o0] = __float2half_rn(lo); g_U1[o1] = __float2half_rn(hi);
        upk2(lo, hi, a2); g_U2[o0] = __float2half_rn(lo); g_U2[o1] = __float2half_rn(hi);
        upk2(lo, hi, a3); g_U3[o0] = __float2half_rn(lo); g_U3[o1] = __float2half_rn(hi);
    }
}

// -------- K2: focus ratios r = ||v||/||v^3||, 1 kz/thread, + s[b][j] warp partials --------
__global__ __launch_bounds__(256) void k_rnorm() {
    int tid = blockIdx.x * 256 + threadIdx.x;   // 262144 threads
    int b  = tid >> 11;
    int kz = tid & 2047;
    int base = b * 131072 + kz;
    int lane = threadIdx.x & 31;
    int widx = (kz >> 5);                        // 64 warps per b

    float s2a = 0.f, s6a = 0.f, s2b = 0.f, s6b = 0.f, s2c = 0.f, s6c = 0.f;
    for (int j = 0; j < 64; j++) {
        int idx = base + j * 2048;
        float v1 = focus_v(ldh(&g_U1[idx]));
        float v2 = focus_v(ldh(&g_U2[idx]));
        float v3 = focus_v(ldh(&g_U3[idx]));
        float q1 = v1 * v1, c1 = q1 * v1; s2a += q1; s6a = fmaf(c1, c1, s6a);
        float q2 = v2 * v2, c2 = q2 * v2; s2b += q2; s6b = fmaf(c2, c2, s6b);
        float q3 = v3 * v3, c3 = q3 * v3; s2c += q3; s6c = fmaf(c3, c3, s6c);
    }
    float r1 = sqrtf(s2a) * rsqrtf(s6a);
    float r2 = sqrtf(s2b) * rsqrtf(s6b);
    float r3 = sqrtf(s2c) * rsqrtf(s6c);
    g_R1[tid] = r1;
    g_R2[tid] = r2;
    g_R3[tid] = r3;

    for (int j = 0; j < 64; j++) {
        float v = focus_v(ldh(&g_U1[base + j * 2048]));
        float f = r1 * v * v * v;
#pragma unroll
        for (int off = 16; off > 0; off >>= 1)
            f += __shfl_xor_sync(0xffffffffu, f, off);
        if (lane == 0) g_Spart[b * 4096 + j * 64 + widx] = f;
    }
}

// -------- K3: kv, 8-way kz split, 8x4 register tile, double-buffered stages --------
__global__ __launch_bounds__(128) void k_kv() {
    __shared__ __align__(16) float As[2][16 * 68];    // [buf][kk][c]
    __shared__ __align__(16) float Bs[2][16 * 68];    // [buf][kk][d]
    __shared__ float Rs2[256], Rs3[256];
    int h = blockIdx.x, b = blockIdx.y;
    int t = threadIdx.x;
    int c0 = (t >> 4) * 8;      // compute tile: 8 groups of 8 c
    int d0 = (t & 15) * 4;      // 16 groups of 4 d
    int kzbase = h * 256;

    for (int e = t; e < 256; e += 128) {
        Rs2[e] = g_R2[b * 2048 + kzbase + e];
        Rs3[e] = g_R3[b * 2048 + kzbase + e];
    }
    __syncthreads();

    int kkf  = t & 15;
    int cgrp = t >> 4;
    int gbase = b * 131072 + (cgrp * 8) * 2048 + kzbase + kkf;

    float u2p[8], u3p[8];
#pragma unroll
    for (int i = 0; i < 8; i++) {
        u2p[i] = ldh(&g_U2[gbase + i * 2048]);
        u3p[i] = ldh(&g_U3[gbase + i * 2048]);
    }

    ull acc[8][2];
#pragma unroll
    for (int i = 0; i < 8; i++) { acc[i][0] = 0ULL; acc[i][1] = 0ULL; }

    int buf = 0;
    for (int s = 0; s < 16; s++) {
        float r2v = Rs2[s * 16 + kkf];
        float r3v = Rs3[s * 16 + kkf];
        float fa[8], fb[8];
#pragma unroll
        for (int i = 0; i < 8; i++) {
            float v2 = focus_v(u2p[i]);
            float v3 = focus_v(u3p[i]);
            fa[i] = r2v * v2 * v2 * v2;
            fb[i] = r3v * v3 * v3 * v3;
        }
        int soff_smem = kkf * 68 + cgrp * 8;
        *(float4*)&As[buf][soff_smem]     = make_float4(fa[0], fa[1], fa[2], fa[3]);
        *(float4*)&As[buf][soff_smem + 4] = make_float4(fa[4], fa[5], fa[6], fa[7]);
        *(float4*)&Bs[buf][soff_smem]     = make_float4(fb[0], fb[1], fb[2], fb[3]);
        *(float4*)&Bs[buf][soff_smem + 4] = make_float4(fb[4], fb[5], fb[6], fb[7]);
        __syncthreads();

        if (s < 15) {
            int soff = (s + 1) * 16;
#pragma unroll
            for (int i = 0; i < 8; i++) {
                u2p[i] = ldh(&g_U2[gbase + i * 2048 + soff]);
                u3p[i] = ldh(&g_U3[gbase + i * 2048 + soff]);
            }
        }

#pragma unroll
        for (int kk = 0; kk < 16; kk++) {
            float4 av0 = *(const float4*)&As[buf][kk * 68 + c0];
            float4 av1 = *(const float4*)&As[buf][kk * 68 + c0 + 4];
            ulonglong2 bv = *(const ulonglong2*)&Bs[buf][kk * 68 + d0];
            ull a0 = pk2(av0.x, av0.x), a1 = pk2(av0.y, av0.y);
            ull a2 = pk2(av0.z, av0.z), a3 = pk2(av0.w, av0.w);
            ull a4 = pk2(av1.x, av1.x), a5 = pk2(av1.y, av1.y);
            ull a6 = pk2(av1.z, av1.z), a7 = pk2(av1.w, av1.w);
            fma2(acc[0][0], a0, bv.x); fma2(acc[0][1], a0, bv.y);
            fma2(acc[1][0], a1, bv.x); fma2(acc[1][1], a1, bv.y);
            fma2(acc[2][0], a2, bv.x); fma2(acc[2][1], a2, bv.y);
            fma2(acc[3][0], a3, bv.x); fma2(acc[3][1], a3, bv.y);
            fma2(acc[4][0], a4, bv.x); fma2(acc[4][1], a4, bv.y);
            fma2(acc[5][0], a5, bv.x); fma2(acc[5][1], a5, bv.y);
            fma2(acc[6][0], a6, bv.x); fma2(acc[6][1], a6, bv.y);
            fma2(acc[7][0], a7, bv.x); fma2(acc[7][1], a7, bv.y);
        }
        buf ^= 1;
    }
#pragma unroll
    for (int i = 0; i < 8; i++) {
        float l0, h0v, l1, h1v;
        upk2(l0, h0v, acc[i][0]);
        upk2(l1, h1v, acc[i][1]);
        int obase = (h * 128 + b) * 4096 + (c0 + i) * 64 + d0;
        g_KVh[obase + 0] = l0; g_KVh[obase + 1] = h0v;
        g_KVh[obase + 2] = l1; g_KVh[obase + 3] = h1v;
    }
}

// -------- K3b: reduce kv partials once: g_KV = sum_h g_KVh[h] --------
__global__ __launch_bounds__(256) void k_kvred() {
    int e = blockIdx.x * 256 + threadIdx.x;      // over BB*2048 ull pairs
    ull p = 0ULL;
#pragma unroll
    for (int q = 0; q < KVH; q++) {
        int b = e >> 11, r = e & 2047;
        p = add2(p, ((const ull*)g_KVh)[(q * 128 + b) * 2048 + r]);
    }
    ((ull*)g_KV)[e] = p;
}

// -------- K4: xmid with fused z; fp16 Xm output [b][kz][d] via smem transpose --------
__global__ __launch_bounds__(128) void k_xmid() {
    __shared__ __align__(16) ull kvs2[2048];        // kv[c][d-pairs], 16KB
    __shared__ float ss[64];
    __shared__ float stage[64 * 65];    // half-tile transpose staging
    int b = blockIdx.y;
    int t = threadIdx.x;
    int kz = blockIdx.x * 128 + t;

    for (int e = t; e < 2048; e += 128)
        kvs2[e] = ((const ull*)g_KV)[b * 2048 + e];
    if (t < 64) {
        float s = 0.f;
        const float* sp = &g_Spart[b * 4096 + t * 64];
        for (int w = 0; w < 64; w++) s += sp[w];
        ss[t] = s;
    }
    __syncthreads();

    ull xr[32];
#pragma unroll
    for (int d = 0; d < 32; d++) xr[d] = 0ULL;

    float r1 = g_R1[b * 2048 + kz];
    float zacc = 0.f;
    for (int c = 0; c < 64; c++) {
        float v = focus_v(ldh(&g_U1[b * 131072 + c * 2048 + kz]));
        float f = r1 * v * v * v;
        zacc = fmaf(f, ss[c], zacc);
        ull f2v = pk2(f, f);
        const ulonglong2* kp = (const ulonglong2*)&kvs2[c * 32];
#pragma unroll
        for (int d8 = 0; d8 < 16; d8++) {
            ulonglong2 kq = kp[d8];
            fma2(xr[2 * d8],     f2v, kq.x);
            fma2(xr[2 * d8 + 1], f2v, kq.y);
        }
    }
    float z = 1.0f / (zacc + 1.1920929e-07f);

#pragma unroll
    for (int half = 0; half < 2; half++) {
        if ((t >> 6) == half) {
            int row = t & 63;
#pragma unroll
            for (int d2 = 0; d2 < 32; d2++) {
                float lo, hi; upk2(lo, hi, xr[d2]);
                stage[row * 65 + 2 * d2]     = lo * z;
                stage[row * 65 + 2 * d2 + 1] = hi * z;
            }
        }
        __syncthreads();
        for (int e = t; e < 4096; e += 128) {
            int kzi = e >> 6, d = e & 63;
            g_Xm[b * 131072 + (blockIdx.x * 128 + half * 64 + kzi) * 64 + d] =
                __float2half_rn(stage[kzi * 65 + d]);
        }
        __syncthreads();
    }
}

// -------- K5: conv-as-GEMM with A' + fused squash; 8-way batch split --------
__global__ __launch_bounds__(256) void k_convsq(const float* __restrict__ conv_b,
                                                float* __restrict__ out) {
    __shared__ __align__(16) float As[32 * 68];   // [ol][d]
    __shared__ __align__(16) float Xs[16 * 68];   // [bb][d]
    int t  = threadIdx.x;
    int o  = t & 31;
    int bg = t >> 5;                 // 8 warps, 2 batches each
    int b0 = blockIdx.x * 16;
    int g  = blockIdx.y;

    ull acc[2] = {0ULL, 0ULL};

    for (int ci = 0; ci < 32; ci++) {
        for (int e = t; e < 2048; e += 256) {
            int ol = e >> 6, d = e & 63;
            As[ol * 68 + d] = g_A[((g * 32 + ol) * 32 + ci) * 64 + d];
        }
        for (int e = t; e < 1024; e += 256) {
            int bb = e >> 6, d = e & 63;
            Xs[bb * 68 + d] = ldh(&g_Xm[(b0 + bb) * 131072 + (g * 32 + ci) * 64 + d]);
        }
        __syncthreads();
        const ulonglong2* ap = (const ulonglong2*)&As[o * 68];
#pragma unroll
        for (int k8 = 0; k8 < 16; k8++) {
            ulonglong2 av = ap[k8];
#pragma unroll
            for (int jb = 0; jb < 2; jb++) {
                ulonglong2 xv = *(const ulonglong2*)&Xs[(bg * 2 + jb) * 68 + k8 * 4];
                fma2(acc[jb], av.x, xv.x);
                fma2(acc[jb], av.y, xv.y);
            }
        }
        __syncthreads();
    }

    int og = g * 32 + o;
    float bias = 64.0f * conv_b[og];
#pragma unroll
    for (int jb = 0; jb < 2; jb++) {
        float lo, hi; upk2(lo, hi, acc[jb]);
        float val = lo + hi + bias;
        float sq = val * val;
#pragma unroll
        for (int off = 16; off > 0; off >>= 1)
            sq += __shfl_xor_sync(0xffffffffu, sq, off);
        float norm = sqrtf(sq);
        float coef = 1.0f - 1.0f / (expf(norm) + 1e-20f);
        out[(b0 + bg * 2 + jb) * 2048 + og] = coef * val / (norm + 1e-20f);
    }
}

extern "C" void kernel_launch(void* const* d_in, const int* in_sizes, int n_in,
                              void* d_out, int out_size) {
    const float* x1     = (const float*)d_in[0];
    const float* x2     = (const float*)d_in[1];
    const float* x3     = (const float*)d_in[2];
    const float* W      = (const float*)d_in[3];
    const float* conv_w = (const float*)d_in[4];
    const float* conv_b = (const float*)d_in[5];
    float* out = (float*)d_out;

    k_prepA    <<<65536 / 256, 256>>>(conv_w);
    k_transform<<<dim3(16, 64), 128>>>(x1, x2, x3, W);
    k_rnorm    <<<262144 / 256, 256>>>();
    k_kv       <<<dim3(KVH, BB), 128>>>();
    k_kvred    <<<(BB * 2048) / 256, 256>>>();
    k_xmid     <<<dim3(16, BB), 128>>>();
    k_convsq   <<<dim3(8, 64), 256>>>(conv_b, out);
}

// round 16
// speedup vs baseline: 1.5070x; 1.5070x over previous
#include <cuda_runtime.h>
#include <cuda_fp16.h>
#include <math.h>

typedef unsigned long long ull;

// Problem constants
#define BB   128
#define NN0  64      // positions (j / c / d)
#define DD0  32      // i
#define CC   2048    // channels kz = n1*32 + d1
#define KC   65
#define KVH  8       // kv split factor

// -------- scratch (device globals) --------
__device__ float  g_A [CC * DD0 * NN0];          // A'[o][ci][d]
__device__ __half g_U1[BB * NN0 * CC];           // [b][j][kz] fp16 storage
__device__ __half g_U2[BB * NN0 * CC];
__device__ __half g_U3[BB * NN0 * CC];
__device__ float  g_R1[BB * CC];
__device__ float  g_R2[BB * CC];
__device__ float  g_R3[BB * CC];
__device__ float  g_Spart[BB * NN0 * 64];        // per-warp partials of s[b][j]
__device__ float  g_KVh[KVH * BB * NN0 * NN0];   // split-k kv partials [h][b][c][d]
__device__ float  g_KV [BB * NN0 * NN0];         // reduced kv [b][c][d]
__device__ __half g_Xm[BB * CC * NN0];           // [b][kz][d] fp16 (d contiguous)

// -------- f32x2 helpers --------
__device__ __forceinline__ ull pk2(float lo, float hi) {
    ull r; asm("mov.b64 %0, {%1, %2};" : "=l"(r) : "f"(lo), "f"(hi)); return r;
}
__device__ __forceinline__ void upk2(float& lo, float& hi, ull v) {
    asm("mov.b64 {%0, %1}, %2;" : "=f"(lo), "=f"(hi) : "l"(v));
}
__device__ __forceinline__ void fma2(ull& acc, ull a, ull b) {
    asm("fma.rn.f32x2 %0, %1, %2, %3;" : "=l"(acc) : "l"(a), "l"(b), "l"(acc));
}
__device__ __forceinline__ ull add2(ull a, ull b) {
    ull r; asm("add.rn.f32x2 %0, %1, %2;" : "=l"(r) : "l"(a), "l"(b)); return r;
}

__device__ __forceinline__ float focus_v(float u) {
    return fmaf(fmaxf(u, 0.0f), 0.2f, 2e-7f);   // (relu(u)+1e-6)/5
}
__device__ __forceinline__ float ldh(const __half* p) { return __half2float(*p); }

// -------- K0: A'[o][ci][d] = window-sum of conv_w + identity --------
__global__ void k_prepA(const float* __restrict__ cw) {
    int tid = blockIdx.x * 256 + threadIdx.x;   // 65536
    int o = tid >> 5, ci = tid & 31;
    const float* wr = cw + (o * 32 + ci) * 65;
    float id = (ci == (o & 31)) ? 1.0f : 0.0f;
    float* ar = g_A + (o * 32 + ci) * 64;
    float s = 0.f;
    for (int k = 0; k <= 32; k++) s += wr[k];
    ar[0] = s + id;
    for (int p = 1; p < 64; p++) {
        int addk = p + 32;
        if (addk <= 64) s += wr[addk];
        int rmk = p - 32;
        if (rmk >= 0) s -= wr[rmk];
        ar[p] = s + id;
    }
}

// -------- K1: transform, f32x2 paired over batch; fp16 U stores --------
__global__ __launch_bounds__(128) void k_transform(
    const float* __restrict__ x1, const float* __restrict__ x2, const float* __restrict__ x3,
    const float* __restrict__ W)
{
    __shared__ __align__(16) ull xs[3][64][32];   // b-pairs, 48KB
    int t  = threadIdx.x;
    int j  = blockIdx.y;
    int kz = blockIdx.x * 128 + t;

    for (int e = t; e < 64 * 32; e += 128) {
        int bp = e >> 5, i = e & 31;
        int s0 = (2 * bp) * 2048 + j * 32 + i, s1 = s0 + 2048;
        xs[0][bp][i] = pk2(x1[s0], x1[s1]);
        xs[1][bp][i] = pk2(x2[s0], x2[s1]);
        xs[2][bp][i] = pk2(x3[s0], x3[s1]);
    }

    ull w2[32];
    int wbase = (kz >> 5) * 65536 + j * 1024 + (kz & 31);
#pragma unroll
    for (int i = 0; i < 32; i++) { float w = W[wbase + i * 32]; w2[i] = pk2(w, w); }

    __syncthreads();

    for (int bp = 0; bp < 64; bp++) {
        ull a1 = 0ULL, a2 = 0ULL, a3 = 0ULL;
        const ulonglong2* p0 = (const ulonglong2*)xs[0][bp];
        const ulonglong2* p1 = (const ulonglong2*)xs[1][bp];
        const ulonglong2* p2 = (const ulonglong2*)xs[2][bp];
#pragma unroll
        for (int q = 0; q < 16; q++) {
            ulonglong2 v0 = p0[q], v1 = p1[q], v2 = p2[q];
            fma2(a1, w2[2 * q], v0.x); fma2(a1, w2[2 * q + 1], v0.y);
            fma2(a2, w2[2 * q], v1.x); fma2(a2, w2[2 * q + 1], v1.y);
            fma2(a3, w2[2 * q], v2.x); fma2(a3, w2[2 * q + 1], v2.y);
        }
        float lo, hi;
        int o0 = (2 * bp) * 131072 + j * 2048 + kz, o1 = o0 + 131072;
        upk2(lo, hi, a1); g_U1[o0] = __float2half_rn(lo); g_U1[o1] = __float2half_rn(hi);
        upk2(lo, hi, a2); g_U2[o0] = __float2half_rn(lo); g_U2[o1] = __float2half_rn(hi);
        upk2(lo, hi, a3); g_U3[o0] = __float2half_rn(lo); g_U3[o1] = __float2half_rn(hi);
    }
}

// -------- K2: focus ratios r = ||v||/||v^3||, 1 kz/thread, + s[b][j] warp partials --------
__global__ __launch_bounds__(256) void k_rnorm() {
    int tid = blockIdx.x * 256 + threadIdx.x;   // 262144 threads
    int b  = tid >> 11;
    int kz = tid & 2047;
    int base = b * 131072 + kz;
    int lane = threadIdx.x & 31;
    int widx = (kz >> 5);                        // 64 warps per b

    float s2a = 0.f, s6a = 0.f, s2b = 0.f, s6b = 0.f, s2c = 0.f, s6c = 0.f;
    for (int j = 0; j < 64; j++) {
        int idx = base + j * 2048;
        float v1 = focus_v(ldh(&g_U1[idx]));
        float v2 = focus_v(ldh(&g_U2[idx]));
        float v3 = focus_v(ldh(&g_U3[idx]));
        float q1 = v1 * v1, c1 = q1 * v1; s2a += q1; s6a = fmaf(c1, c1, s6a);
        float q2 = v2 * v2, c2 = q2 * v2; s2b += q2; s6b = fmaf(c2, c2, s6b);
        float q3 = v3 * v3, c3 = q3 * v3; s2c += q3; s6c = fmaf(c3, c3, s6c);
    }
    float r1 = sqrtf(s2a) * rsqrtf(s6a);
    float r2 = sqrtf(s2b) * rsqrtf(s6b);
    float r3 = sqrtf(s2c) * rsqrtf(s6c);
    g_R1[tid] = r1;
    g_R2[tid] = r2;
    g_R3[tid] = r3;

    for (int j = 0; j < 64; j++) {
        float v = focus_v(ldh(&g_U1[base + j * 2048]));
        float f = r1 * v * v * v;
#pragma unroll
        for (int off = 16; off > 0; off >>= 1)
            f += __shfl_xor_sync(0xffffffffu, f, off);
        if (lane == 0) g_Spart[b * 4096 + j * 64 + widx] = f;
    }
}

// -------- K3: kv, 8-way kz split, 8x4 register tile, double-buffered stages --------
__global__ __launch_bounds__(128) void k_kv() {
    __shared__ __align__(16) float As[2][16 * 68];    // [buf][kk][c]
    __shared__ __align__(16) float Bs[2][16 * 68];    // [buf][kk][d]
    __shared__ float Rs2[256], Rs3[256];
    int h = blockIdx.x, b = blockIdx.y;
    int t = threadIdx.x;
    int c0 = (t >> 4) * 8;      // compute tile: 8 groups of 8 c
    int d0 = (t & 15) * 4;      // 16 groups of 4 d
    int kzbase = h * 256;

    for (int e = t; e < 256; e += 128) {
        Rs2[e] = g_R2[b * 2048 + kzbase + e];
        Rs3[e] = g_R3[b * 2048 + kzbase + e];
    }
    __syncthreads();

    int kkf  = t & 15;
    int cgrp = t >> 4;
    int gbase = b * 131072 + (cgrp * 8) * 2048 + kzbase + kkf;

    float u2p[8], u3p[8];
#pragma unroll
    for (int i = 0; i < 8; i++) {
        u2p[i] = ldh(&g_U2[gbase + i * 2048]);
        u3p[i] = ldh(&g_U3[gbase + i * 2048]);
    }

    ull acc[8][2];
#pragma unroll
    for (int i = 0; i < 8; i++) { acc[i][0] = 0ULL; acc[i][1] = 0ULL; }

    int buf = 0;
    for (int s = 0; s < 16; s++) {
        float r2v = Rs2[s * 16 + kkf];
        float r3v = Rs3[s * 16 + kkf];
        float fa[8], fb[8];
#pragma unroll
        for (int i = 0; i < 8; i++) {
            float v2 = focus_v(u2p[i]);
            float v3 = focus_v(u3p[i]);
            fa[i] = r2v * v2 * v2 * v2;
            fb[i] = r3v * v3 * v3 * v3;
        }
        int soff_smem = kkf * 68 + cgrp * 8;
        *(float4*)&As[buf][soff_smem]     = make_float4(fa[0], fa[1], fa[2], fa[3]);
        *(float4*)&As[buf][soff_smem + 4] = make_float4(fa[4], fa[5], fa[6], fa[7]);
        *(float4*)&Bs[buf][soff_smem]     = make_float4(fb[0], fb[1], fb[2], fb[3]);
        *(float4*)&Bs[buf][soff_smem + 4] = make_float4(fb[4], fb[5], fb[6], fb[7]);
        __syncthreads();

        if (s < 15) {
            int soff = (s + 1) * 16;
#pragma unroll
            for (int i = 0; i < 8; i++) {
                u2p[i] = ldh(&g_U2[gbase + i * 2048 + soff]);
                u3p[i] = ldh(&g_U3[gbase + i * 2048 + soff]);
            }
        }

#pragma unroll
        for (int kk = 0; kk < 16; kk++) {
            float4 av0 = *(const float4*)&As[buf][kk * 68 + c0];
            float4 av1 = *(const float4*)&As[buf][kk * 68 + c0 + 4];
            ulonglong2 bv = *(const ulonglong2*)&Bs[buf][kk * 68 + d0];
            ull a0 = pk2(av0.x, av0.x), a1 = pk2(av0.y, av0.y);
            ull a2 = pk2(av0.z, av0.z), a3 = pk2(av0.w, av0.w);
            ull a4 = pk2(av1.x, av1.x), a5 = pk2(av1.y, av1.y);
            ull a6 = pk2(av1.z, av1.z), a7 = pk2(av1.w, av1.w);
            fma2(acc[0][0], a0, bv.x); fma2(acc[0][1], a0, bv.y);
            fma2(acc[1][0], a1, bv.x); fma2(acc[1][1], a1, bv.y);
            fma2(acc[2][0], a2, bv.x); fma2(acc[2][1], a2, bv.y);
            fma2(acc[3][0], a3, bv.x); fma2(acc[3][1], a3, bv.y);
            fma2(acc[4][0], a4, bv.x); fma2(acc[4][1], a4, bv.y);
            fma2(acc[5][0], a5, bv.x); fma2(acc[5][1], a5, bv.y);
            fma2(acc[6][0], a6, bv.x); fma2(acc[6][1], a6, bv.y);
            fma2(acc[7][0], a7, bv.x); fma2(acc[7][1], a7, bv.y);
        }
        buf ^= 1;
    }
#pragma unroll
    for (int i = 0; i < 8; i++) {
        float l0, h0v, l1, h1v;
        upk2(l0, h0v, acc[i][0]);
        upk2(l1, h1v, acc[i][1]);
        int obase = (h * 128 + b) * 4096 + (c0 + i) * 64 + d0;
        g_KVh[obase + 0] = l0; g_KVh[obase + 1] = h0v;
        g_KVh[obase + 2] = l1; g_KVh[obase + 3] = h1v;
    }
}

// -------- K3b: reduce kv partials once: g_KV = sum_h g_KVh[h] --------
__global__ __launch_bounds__(256) void k_kvred() {
    int e = blockIdx.x * 256 + threadIdx.x;      // over BB*2048 ull pairs
    ull p = 0ULL;
#pragma unroll
    for (int q = 0; q < KVH; q++) {
        int b = e >> 11, r = e & 2047;
        p = add2(p, ((const ull*)g_KVh)[(q * 128 + b) * 2048 + r]);
    }
    ((ull*)g_KV)[e] = p;
}

// -------- K4: xmid with fused z; fp16 Xm output [b][kz][d] via smem transpose --------
__global__ __launch_bounds__(128) void k_xmid() {
    __shared__ __align__(16) ull kvs2[2048];        // kv[c][d-pairs], 16KB
    __shared__ float ss[64];
    __shared__ float stage[64 * 65];    // half-tile transpose staging
    int b = blockIdx.y;
    int t = threadIdx.x;
    int kz = blockIdx.x * 128 + t;

    for (int e = t; e < 2048; e += 128)
        kvs2[e] = ((const ull*)g_KV)[b * 2048 + e];
    if (t < 64) {
        float s = 0.f;
        const float* sp = &g_Spart[b * 4096 + t * 64];
        for (int w = 0; w < 64; w++) s += sp[w];
        ss[t] = s;
    }
    __syncthreads();

    ull xr[32];
#pragma unroll
    for (int d = 0; d < 32; d++) xr[d] = 0ULL;

    float r1 = g_R1[b * 2048 + kz];
    float zacc = 0.f;
    for (int c = 0; c < 64; c++) {
        float v = focus_v(ldh(&g_U1[b * 131072 + c * 2048 + kz]));
        float f = r1 * v * v * v;
        zacc = fmaf(f, ss[c], zacc);
        ull f2v = pk2(f, f);
        const ulonglong2* kp = (const ulonglong2*)&kvs2[c * 32];
#pragma unroll
        for (int d8 = 0; d8 < 16; d8++) {
            ulonglong2 kq = kp[d8];
            fma2(xr[2 * d8],     f2v, kq.x);
            fma2(xr[2 * d8 + 1], f2v, kq.y);
        }
    }
    float z = 1.0f / (zacc + 1.1920929e-07f);

#pragma unroll
    for (int half = 0; half < 2; half++) {
        if ((t >> 6) == half) {
            int row = t & 63;
#pragma unroll
            for (int d2 = 0; d2 < 32; d2++) {
                float lo, hi; upk2(lo, hi, xr[d2]);
                stage[row * 65 + 2 * d2]     = lo * z;
                stage[row * 65 + 2 * d2 + 1] = hi * z;
            }
        }
        __syncthreads();
        for (int e = t; e < 4096; e += 128) {
            int kzi = e >> 6, d = e & 63;
            g_Xm[b * 131072 + (blockIdx.x * 128 + half * 64 + kzi) * 64 + d] =
                __float2half_rn(stage[kzi * 65 + d]);
        }
        __syncthreads();
    }
}

// -------- K5: conv-as-GEMM with A' + fused squash; 8-way batch split --------
__global__ __launch_bounds__(256) void k_convsq(const float* __restrict__ conv_b,
                                                float* __restrict__ out) {
    __shared__ __align__(16) float As[32 * 68];   // [ol][d]
    __shared__ __align__(16) float Xs[16 * 68];   // [bb][d]
    int t  = threadIdx.x;
    int o  = t & 31;
    int bg = t >> 5;                 // 8 warps, 2 batches each
    int b0 = blockIdx.x * 16;
    int g  = blockIdx.y;

    ull acc[2] = {0ULL, 0ULL};

    for (int ci = 0; ci < 32; ci++) {
        for (int e = t; e < 2048; e += 256) {
            int ol = e >> 6, d = e & 63;
            As[ol * 68 + d] = g_A[((g * 32 + ol) * 32 + ci) * 64 + d];
        }
        for (int e = t; e < 1024; e += 256) {
            int bb = e >> 6, d = e & 63;
            Xs[bb * 68 + d] = ldh(&g_Xm[(b0 + bb) * 131072 + (g * 32 + ci) * 64 + d]);
        }
        __syncthreads();
        const ulonglong2* ap = (const ulonglong2*)&As[o * 68];
#pragma unroll
        for (int k8 = 0; k8 < 16; k8++) {
            ulonglong2 av = ap[k8];
#pragma unroll
            for (int jb = 0; jb < 2; jb++) {
                ulonglong2 xv = *(const ulonglong2*)&Xs[(bg * 2 + jb) * 68 + k8 * 4];
                fma2(acc[jb], av.x, xv.x);
                fma2(acc[jb], av.y, xv.y);
            }
        }
        __syncthreads();
    }

    int og = g * 32 + o;
    float bias = 64.0f * conv_b[og];
#pragma unroll
    for (int jb = 0; jb < 2; jb++) {
        float lo, hi; upk2(lo, hi, acc[jb]);
        float val = lo + hi + bias;
        float sq = val * val;
#pragma unroll
        for (int off = 16; off > 0; off >>= 1)
            sq += __shfl_xor_sync(0xffffffffu, sq, off);
        float norm = sqrtf(sq);
        float coef = 1.0f - 1.0f / (expf(norm) + 1e-20f);
        out[(b0 + bg * 2 + jb) * 2048 + og] = coef * val / (norm + 1e-20f);
    }
}

extern "C" void kernel_launch(void* const* d_in, const int* in_sizes, int n_in,
                              void* d_out, int out_size) {
    const float* x1     = (const float*)d_in[0];
    const float* x2     = (const float*)d_in[1];
    const float* x3     = (const float*)d_in[2];
    const float* W      = (const float*)d_in[3];
    const float* conv_w = (const float*)d_in[4];
    const float* conv_b = (const float*)d_in[5];
    float* out = (float*)d_out;

    k_prepA    <<<65536 / 256, 256>>>(conv_w);
    k_transform<<<dim3(16, 64), 128>>>(x1, x2, x3, W);
    k_rnorm    <<<262144 / 256, 256>>>();
    k_kv       <<<dim3(KVH, BB), 128>>>();
    k_kvred    <<<(BB * 2048) / 256, 256>>>();
    k_xmid     <<<dim3(16, BB), 128>>>();
    k_convsq   <<<dim3(8, 64), 256>>>(conv_b, out);
}

// round 17
// speedup vs baseline: 1.5812x; 1.0492x over previous
#include <cuda_runtime.h>
#include <cuda_fp16.h>
#include <math.h>

typedef unsigned long long ull;

// Problem constants
#define BB   128
#define NN0  64      // positions (j / c / d)
#define DD0  32      // i
#define CC   2048    // channels kz = n1*32 + d1
#define KC   65
#define KVH  8       // kv split factor

// -------- scratch (device globals) --------
__device__ float   g_A [CC * DD0 * NN0];          // A'[o][ci][d]
__device__ __half  g_U1[BB * NN0 * CC];           // [b][j][kz] fp16
__device__ __half2 g_U23[BB * NN0 * CC];          // [b][j][kz] packed (u2,u3)
__device__ float   g_R1[BB * CC];
__device__ float   g_R2[BB * CC];
__device__ float   g_R3[BB * CC];
__device__ float   g_Spart[BB * NN0 * 64];        // per-warp partials of s[b][j]
__device__ float   g_KVh[KVH * BB * NN0 * NN0];   // split-k kv partials [h][b][c][d]
__device__ float   g_KV [BB * NN0 * NN0];         // reduced kv [b][c][d]
__device__ __half  g_Xm[BB * CC * NN0];           // [b][kz][d] fp16 (d contiguous)

// -------- f32x2 helpers --------
__device__ __forceinline__ ull pk2(float lo, float hi) {
    ull r; asm("mov.b64 %0, {%1, %2};" : "=l"(r) : "f"(lo), "f"(hi)); return r;
}
__device__ __forceinline__ void upk2(float& lo, float& hi, ull v) {
    asm("mov.b64 {%0, %1}, %2;" : "=f"(lo), "=f"(hi) : "l"(v));
}
__device__ __forceinline__ void fma2(ull& acc, ull a, ull b) {
    asm("fma.rn.f32x2 %0, %1, %2, %3;" : "=l"(acc) : "l"(a), "l"(b), "l"(acc));
}
__device__ __forceinline__ ull add2(ull a, ull b) {
    ull r; asm("add.rn.f32x2 %0, %1, %2;" : "=l"(r) : "l"(a), "l"(b)); return r;
}

__device__ __forceinline__ float focus_v(float u) {
    return fmaf(fmaxf(u, 0.0f), 0.2f, 2e-7f);   // (relu(u)+1e-6)/5
}
__device__ __forceinline__ float ldh(const __half* p) { return __half2float(*p); }

// -------- K0: A'[o][ci][d] = window-sum of conv_w + identity --------
__global__ void k_prepA(const float* __restrict__ cw) {
    int tid = blockIdx.x * 256 + threadIdx.x;   // 65536
    int o = tid >> 5, ci = tid & 31;
    const float* wr = cw + (o * 32 + ci) * 65;
    float id = (ci == (o & 31)) ? 1.0f : 0.0f;
    float* ar = g_A + (o * 32 + ci) * 64;
    float s = 0.f;
    for (int k = 0; k <= 32; k++) s += wr[k];
    ar[0] = s + id;
    for (int p = 1; p < 64; p++) {
        int addk = p + 32;
        if (addk <= 64) s += wr[addk];
        int rmk = p - 32;
        if (rmk >= 0) s -= wr[rmk];
        ar[p] = s + id;
    }
}

// -------- K1: transform, f32x2 paired over batch; fp16 U stores (U23 packed) --------
__global__ __launch_bounds__(128) void k_transform(
    const float* __restrict__ x1, const float* __restrict__ x2, const float* __restrict__ x3,
    const float* __restrict__ W)
{
    __shared__ __align__(16) ull xs[3][64][32];   // b-pairs, 48KB
    int t  = threadIdx.x;
    int j  = blockIdx.y;
    int kz = blockIdx.x * 128 + t;

    for (int e = t; e < 64 * 32; e += 128) {
        int bp = e >> 5, i = e & 31;
        int s0 = (2 * bp) * 2048 + j * 32 + i, s1 = s0 + 2048;
        xs[0][bp][i] = pk2(x1[s0], x1[s1]);
        xs[1][bp][i] = pk2(x2[s0], x2[s1]);
        xs[2][bp][i] = pk2(x3[s0], x3[s1]);
    }

    ull w2[32];
    int wbase = (kz >> 5) * 65536 + j * 1024 + (kz & 31);
#pragma unroll
    for (int i = 0; i < 32; i++) { float w = W[wbase + i * 32]; w2[i] = pk2(w, w); }

    __syncthreads();

    for (int bp = 0; bp < 64; bp++) {
        ull a1 = 0ULL, a2 = 0ULL, a3 = 0ULL;
        const ulonglong2* p0 = (const ulonglong2*)xs[0][bp];
        const ulonglong2* p1 = (const ulonglong2*)xs[1][bp];
        const ulonglong2* p2 = (const ulonglong2*)xs[2][bp];
#pragma unroll
        for (int q = 0; q < 16; q++) {
            ulonglong2 v0 = p0[q], v1 = p1[q], v2 = p2[q];
            fma2(a1, w2[2 * q], v0.x); fma2(a1, w2[2 * q + 1], v0.y);
            fma2(a2, w2[2 * q], v1.x); fma2(a2, w2[2 * q + 1], v1.y);
            fma2(a3, w2[2 * q], v2.x); fma2(a3, w2[2 * q + 1], v2.y);
        }
        float lo1, hi1, lo2, hi2, lo3, hi3;
        int o0 = (2 * bp) * 131072 + j * 2048 + kz, o1 = o0 + 131072;
        upk2(lo1, hi1, a1);
        upk2(lo2, hi2, a2);
        upk2(lo3, hi3, a3);
        g_U1[o0] = __float2half_rn(lo1);
        g_U1[o1] = __float2half_rn(hi1);
        g_U23[o0] = __halves2half2(__float2half_rn(lo2), __float2half_rn(lo3));
        g_U23[o1] = __halves2half2(__float2half_rn(hi2), __float2half_rn(hi3));
    }
}

// -------- K2: focus ratios r = ||v||/||v^3||, 1 kz/thread, + s[b][j] warp partials --------
__global__ __launch_bounds__(256) void k_rnorm() {
    int tid = blockIdx.x * 256 + threadIdx.x;   // 262144 threads
    int b  = tid >> 11;
    int kz = tid & 2047;
    int base = b * 131072 + kz;
    int lane = threadIdx.x & 31;
    int widx = (kz >> 5);                        // 64 warps per b

    float s2a = 0.f, s6a = 0.f, s2b = 0.f, s6b = 0.f, s2c = 0.f, s6c = 0.f;
    for (int j = 0; j < 64; j++) {
        int idx = base + j * 2048;
        float v1 = focus_v(ldh(&g_U1[idx]));
        __half2 h23 = g_U23[idx];
        float v2 = focus_v(__low2float(h23));
        float v3 = focus_v(__high2float(h23));
        float q1 = v1 * v1, c1 = q1 * v1; s2a += q1; s6a = fmaf(c1, c1, s6a);
        float q2 = v2 * v2, c2 = q2 * v2; s2b += q2; s6b = fmaf(c2, c2, s6b);
        float q3 = v3 * v3, c3 = q3 * v3; s2c += q3; s6c = fmaf(c3, c3, s6c);
    }
    float r1 = sqrtf(s2a) * rsqrtf(s6a);
    float r2 = sqrtf(s2b) * rsqrtf(s6b);
    float r3 = sqrtf(s2c) * rsqrtf(s6c);
    g_R1[tid] = r1;
    g_R2[tid] = r2;
    g_R3[tid] = r3;

    for (int j = 0; j < 64; j++) {
        float v = focus_v(ldh(&g_U1[base + j * 2048]));
        float f = r1 * v * v * v;
#pragma unroll
        for (int off = 16; off > 0; off >>= 1)
            f += __shfl_xor_sync(0xffffffffu, f, off);
        if (lane == 0) g_Spart[b * 4096 + j * 64 + widx] = f;
    }
}

// -------- K3: kv, 8-way kz split, 8x4 register tile, double-buffered stages --------
// Fill reads packed (u2,u3) __half2 -> half the LDG count.
__global__ __launch_bounds__(128) void k_kv() {
    __shared__ __align__(16) float As[2][16 * 68];    // [buf][kk][c]
    __shared__ __align__(16) float Bs[2][16 * 68];    // [buf][kk][d]
    __shared__ float Rs2[256], Rs3[256];
    int h = blockIdx.x, b = blockIdx.y;
    int t = threadIdx.x;
    int c0 = (t >> 4) * 8;      // compute tile: 8 groups of 8 c
    int d0 = (t & 15) * 4;      // 16 groups of 4 d
    int kzbase = h * 256;

    for (int e = t; e < 256; e += 128) {
        Rs2[e] = g_R2[b * 2048 + kzbase + e];
        Rs3[e] = g_R3[b * 2048 + kzbase + e];
    }
    __syncthreads();

    int kkf  = t & 15;
    int cgrp = t >> 4;
    int gbase = b * 131072 + (cgrp * 8) * 2048 + kzbase + kkf;

    __half2 up[8];
#pragma unroll
    for (int i = 0; i < 8; i++)
        up[i] = g_U23[gbase + i * 2048];

    ull acc[8][2];
#pragma unroll
    for (int i = 0; i < 8; i++) { acc[i][0] = 0ULL; acc[i][1] = 0ULL; }

    int buf = 0;
    for (int s = 0; s < 16; s++) {
        float r2v = Rs2[s * 16 + kkf];
        float r3v = Rs3[s * 16 + kkf];
        float fa[8], fb[8];
#pragma unroll
        for (int i = 0; i < 8; i++) {
            float v2 = focus_v(__low2float(up[i]));
            float v3 = focus_v(__high2float(up[i]));
            fa[i] = r2v * v2 * v2 * v2;
            fb[i] = r3v * v3 * v3 * v3;
        }
        int soff_smem = kkf * 68 + cgrp * 8;
        *(float4*)&As[buf][soff_smem]     = make_float4(fa[0], fa[1], fa[2], fa[3]);
        *(float4*)&As[buf][soff_smem + 4] = make_float4(fa[4], fa[5], fa[6], fa[7]);
        *(float4*)&Bs[buf][soff_smem]     = make_float4(fb[0], fb[1], fb[2], fb[3]);
        *(float4*)&Bs[buf][soff_smem + 4] = make_float4(fb[4], fb[5], fb[6], fb[7]);
        __syncthreads();

        if (s < 15) {
            int soff = (s + 1) * 16;
#pragma unroll
            for (int i = 0; i < 8; i++)
                up[i] = g_U23[gbase + i * 2048 + soff];
        }

#pragma unroll
        for (int kk = 0; kk < 16; kk++) {
            float4 av0 = *(const float4*)&As[buf][kk * 68 + c0];
            float4 av1 = *(const float4*)&As[buf][kk * 68 + c0 + 4];
            ulonglong2 bv = *(const ulonglong2*)&Bs[buf][kk * 68 + d0];
            ull a0 = pk2(av0.x, av0.x), a1 = pk2(av0.y, av0.y);
            ull a2 = pk2(av0.z, av0.z), a3 = pk2(av0.w, av0.w);
            ull a4 = pk2(av1.x, av1.x), a5 = pk2(av1.y, av1.y);
            ull a6 = pk2(av1.z, av1.z), a7 = pk2(av1.w, av1.w);
            fma2(acc[0][0], a0, bv.x); fma2(acc[0][1], a0, bv.y);
            fma2(acc[1][0], a1, bv.x); fma2(acc[1][1], a1, bv.y);
            fma2(acc[2][0], a2, bv.x); fma2(acc[2][1], a2, bv.y);
            fma2(acc[3][0], a3, bv.x); fma2(acc[3][1], a3, bv.y);
            fma2(acc[4][0], a4, bv.x); fma2(acc[4][1], a4, bv.y);
            fma2(acc[5][0], a5, bv.x); fma2(acc[5][1], a5, bv.y);
            fma2(acc[6][0], a6, bv.x); fma2(acc[6][1], a6, bv.y);
            fma2(acc[7][0], a7, bv.x); fma2(acc[7][1], a7, bv.y);
        }
        buf ^= 1;
    }
#pragma unroll
    for (int i = 0; i < 8; i++) {
        float l0, h0v, l1, h1v;
        upk2(l0, h0v, acc[i][0]);
        upk2(l1, h1v, acc[i][1]);
        int obase = (h * 128 + b) * 4096 + (c0 + i) * 64 + d0;
        g_KVh[obase + 0] = l0; g_KVh[obase + 1] = h0v;
        g_KVh[obase + 2] = l1; g_KVh[obase + 3] = h1v;
    }
}

// -------- K3b: reduce kv partials once: g_KV = sum_h g_KVh[h] --------
__global__ __launch_bounds__(256) void k_kvred() {
    int e = blockIdx.x * 256 + threadIdx.x;      // over BB*2048 ull pairs
    ull p = 0ULL;
#pragma unroll
    for (int q = 0; q < KVH; q++) {
        int b = e >> 11, r = e & 2047;
        p = add2(p, ((const ull*)g_KVh)[(q * 128 + b) * 2048 + r]);
    }
    ((ull*)g_KV)[e] = p;
}

// -------- K4: xmid with fused z; fp16 Xm output [b][kz][d] via smem transpose --------
__global__ __launch_bounds__(128) void k_xmid() {
    __shared__ __align__(16) ull kvs2[2048];        // kv[c][d-pairs], 16KB
    __shared__ float ss[64];
    __shared__ float stage[64 * 65];    // half-tile transpose staging
    int b = blockIdx.y;
    int t = threadIdx.x;
    int kz = blockIdx.x * 128 + t;

    for (int e = t; e < 2048; e += 128)
        kvs2[e] = ((const ull*)g_KV)[b * 2048 + e];
    if (t < 64) {
        float s = 0.f;
        const float* sp = &g_Spart[b * 4096 + t * 64];
        for (int w = 0; w < 64; w++) s += sp[w];
        ss[t] = s;
    }
    __syncthreads();

    ull xr[32];
#pragma unroll
    for (int d = 0; d < 32; d++) xr[d] = 0ULL;

    float r1 = g_R1[b * 2048 + kz];
    float zacc = 0.f;
    for (int c = 0; c < 64; c++) {
        float v = focus_v(ldh(&g_U1[b * 131072 + c * 2048 + kz]));
        float f = r1 * v * v * v;
        zacc = fmaf(f, ss[c], zacc);
        ull f2v = pk2(f, f);
        const ulonglong2* kp = (const ulonglong2*)&kvs2[c * 32];
#pragma unroll
        for (int d8 = 0; d8 < 16; d8++) {
            ulonglong2 kq = kp[d8];
            fma2(xr[2 * d8],     f2v, kq.x);
            fma2(xr[2 * d8 + 1], f2v, kq.y);
        }
    }
    float z = 1.0f / (zacc + 1.1920929e-07f);

#pragma unroll
    for (int half = 0; half < 2; half++) {
        if ((t >> 6) == half) {
            int row = t & 63;
#pragma unroll
            for (int d2 = 0; d2 < 32; d2++) {
                float lo, hi; upk2(lo, hi, xr[d2]);
                stage[row * 65 + 2 * d2]     = lo * z;
                stage[row * 65 + 2 * d2 + 1] = hi * z;
            }
        }
        __syncthreads();
        for (int e = t; e < 4096; e += 128) {
            int kzi = e >> 6, d = e & 63;
            g_Xm[b * 131072 + (blockIdx.x * 128 + half * 64 + kzi) * 64 + d] =
                __float2half_rn(stage[kzi * 65 + d]);
        }
        __syncthreads();
    }
}

// -------- K5: conv-as-GEMM with A' + fused squash; 8-way batch split --------
__global__ __launch_bounds__(256) void k_convsq(const float* __restrict__ conv_b,
                                                float* __restrict__ out) {
    __shared__ __align__(16) float As[32 * 68];   // [ol][d]
    __shared__ __align__(16) float Xs[16 * 68];   // [bb][d]
    int t  = threadIdx.x;
    int o  = t & 31;
    int bg = t >> 5;                 // 8 warps, 2 batches each
    int b0 = blockIdx.x * 16;
    int g  = blockIdx.y;

    ull acc[2] = {0ULL, 0ULL};

    for (int ci = 0; ci < 32; ci++) {
        for (int e = t; e < 2048; e += 256) {
            int ol = e >> 6, d = e & 63;
            As[ol * 68 + d] = g_A[((g * 32 + ol) * 32 + ci) * 64 + d];
        }
        for (int e = t; e < 1024; e += 256) {
            int bb = e >> 6, d = e & 63;
            Xs[bb * 68 + d] = ldh(&g_Xm[(b0 + bb) * 131072 + (g * 32 + ci) * 64 + d]);
        }
        __syncthreads();
        const ulonglong2* ap = (const ulonglong2*)&As[o * 68];
#pragma unroll
        for (int k8 = 0; k8 < 16; k8++) {
            ulonglong2 av = ap[k8];
#pragma unroll
            for (int jb = 0; jb < 2; jb++) {
                ulonglong2 xv = *(const ulonglong2*)&Xs[(bg * 2 + jb) * 68 + k8 * 4];
                fma2(acc[jb], av.x, xv.x);
                fma2(acc[jb], av.y, xv.y);
            }
        }
        __syncthreads();
    }

    int og = g * 32 + o;
    float bias = 64.0f * conv_b[og];
#pragma unroll
    for (int jb = 0; jb < 2; jb++) {
        float lo, hi; upk2(lo, hi, acc[jb]);
        float val = lo + hi + bias;
        float sq = val * val;
#pragma unroll
        for (int off = 16; off > 0; off >>= 1)
            sq += __shfl_xor_sync(0xffffffffu, sq, off);
        float norm = sqrtf(sq);
        float coef = 1.0f - 1.0f / (expf(norm) + 1e-20f);
        out[(b0 + bg * 2 + jb) * 2048 + og] = coef * val / (norm + 1e-20f);
    }
}

extern "C" void kernel_launch(void* const* d_in, const int* in_sizes, int n_in,
                              void* d_out, int out_size) {
    const float* x1     = (const float*)d_in[0];
    const float* x2     = (const float*)d_in[1];
    const float* x3     = (const float*)d_in[2];
    const float* W      = (const float*)d_in[3];
    const float* conv_w = (const float*)d_in[4];
    const float* conv_b = (const float*)d_in[5];
    float* out = (float*)d_out;

    k_prepA    <<<65536 / 256, 256>>>(conv_w);
    k_transform<<<dim3(16, 64), 128>>>(x1, x2, x3, W);
    k_rnorm    <<<262144 / 256, 256>>>();
    k_kv       <<<dim3(KVH, BB), 128>>>();
    k_kvred    <<<(BB * 2048) / 256, 256>>>();
    k_xmid     <<<dim3(16, BB), 128>>>();
    k_convsq   <<<dim3(8, 64), 256>>>(conv_b, out);
}